// round 1
// baseline (speedup 1.0000x reference)
#include <cuda_runtime.h>

#define B_  2
#define S_  2048
#define D_  1024
#define H_  16
#define HD_ 64
#define M_  (B_*S_)   // 4096

// Scratch (allocation-free rule: __device__ globals)
__device__ float g_q[B_*H_*S_*HD_];   // [b,h,s,hd]
__device__ float g_k[B_*H_*S_*HD_];
__device__ float g_v[B_*H_*S_*HD_];
__device__ float g_ao[M_*D_];         // attention out, [b,s, h*hd]

// ---------------------------------------------------------------------------
// SGEMM: C[m][n] = sum_k A[m][k] * W[k][n] + bias[n]
// MODE 0: A := g_ao, out := outp (row-major [M, D])
// MODE 1/2/3: A := param (x), out := g_q/g_k/g_v in [b,h,s,hd] layout
// Tile: BM=128, BN=128, BK=16, 256 threads, 8x8 microtile
// ---------------------------------------------------------------------------
template<int MODE>
__global__ __launch_bounds__(256)
void gemm_kernel(const float* __restrict__ Ap,
                 const float* __restrict__ W,
                 const float* __restrict__ bias,
                 float* __restrict__ outp)
{
    __shared__ float As[16][128];
    __shared__ float Bs[16][128];

    const float* A = (MODE == 0) ? (const float*)g_ao : Ap;

    const int tid = threadIdx.x;
    const int tx = tid & 15;         // 0..15  (col group)
    const int ty = tid >> 4;         // 0..15  (row group)
    const int bm = blockIdx.y * 128;
    const int bn = blockIdx.x * 128;

    float acc[8][8];
    #pragma unroll
    for (int i = 0; i < 8; i++)
        #pragma unroll
        for (int j = 0; j < 8; j++) acc[i][j] = 0.f;

    for (int k0 = 0; k0 < D_; k0 += 16) {
        #pragma unroll
        for (int l = 0; l < 2; l++) {
            int id = tid * 2 + l;                 // 0..511
            int ar = id >> 2, ac = (id & 3) * 4;  // A tile: 128 rows x 16 cols
            float4 av = *(const float4*)&A[(size_t)(bm + ar) * D_ + k0 + ac];
            As[ac + 0][ar] = av.x;
            As[ac + 1][ar] = av.y;
            As[ac + 2][ar] = av.z;
            As[ac + 3][ar] = av.w;
            int wr = id >> 5, wc = (id & 31) * 4; // W tile: 16 rows x 128 cols
            *(float4*)&Bs[wr][wc] =
                *(const float4*)&W[(size_t)(k0 + wr) * D_ + bn + wc];
        }
        __syncthreads();

        #pragma unroll
        for (int kk = 0; kk < 16; kk++) {
            float a[8], b[8];
            *(float4*)&a[0] = *(const float4*)&As[kk][ty * 8];
            *(float4*)&a[4] = *(const float4*)&As[kk][ty * 8 + 4];
            *(float4*)&b[0] = *(const float4*)&Bs[kk][tx * 8];
            *(float4*)&b[4] = *(const float4*)&Bs[kk][tx * 8 + 4];
            #pragma unroll
            for (int i = 0; i < 8; i++)
                #pragma unroll
                for (int j = 0; j < 8; j++)
                    acc[i][j] += a[i] * b[j];
        }
        __syncthreads();
    }

    float* qkv_out = (MODE == 1) ? g_q : (MODE == 2) ? g_k : g_v;

    #pragma unroll
    for (int i = 0; i < 8; i++) {
        int m = bm + ty * 8 + i;
        #pragma unroll
        for (int j = 0; j < 8; j++) {
            int n = bn + tx * 8 + j;
            float v = acc[i][j] + bias[n];
            if (MODE == 0) {
                outp[(size_t)m * D_ + n] = v;
            } else {
                int b = m >> 11, s = m & 2047;    // m = b*2048 + s
                int h = n >> 6,  hd = n & 63;
                qkv_out[(((size_t)(b * H_ + h)) * S_ + s) * HD_ + hd] = v;
            }
        }
    }
}

// ---------------------------------------------------------------------------
// Flash attention per (b*H+h, 64-row query tile). Br=Bc=64, 256 threads.
// Thread (ty,tx) owns rows r0=4*ty..+3, cols c0=4*tx..+3 of the 64x64 tile.
// Per-row softmax state (m,l) held redundantly by the 16 threads of a row
// group (same ty = one warp half); reductions via __shfl_xor_sync 1,2,4,8.
// Dynamic smem: Qst/Kst/Pt/Vs each [64][68] (pad 4 keeps float4 alignment,
// breaks the stride-64 bank pattern) = 69632 B total -> 3 CTAs/SM.
// ---------------------------------------------------------------------------
__global__ __launch_bounds__(256)
void attn_kernel()
{
    extern __shared__ float sm[];
    float* Qst = sm;                  // [d][r], pre-scaled by 1/8
    float* Kst = sm + 64 * 68;        // [d][c]
    float* Pt  = sm + 2 * 64 * 68;    // [j][r]
    float* Vs  = sm + 3 * 64 * 68;    // [j][d]

    const int tid = threadIdx.x;
    const int tx = tid & 15, ty = tid >> 4;
    const int r0 = ty * 4, c0 = tx * 4;
    const int bh = blockIdx.y;
    const int q0 = blockIdx.x * 64;

    const float* Qb = g_q + (size_t)bh * S_ * HD_;
    const float* Kb = g_k + (size_t)bh * S_ * HD_;
    const float* Vb = g_v + (size_t)bh * S_ * HD_;

    // Load + transpose Q tile, folding in the 1/sqrt(64) scale
    {
        int r = tid & 63, ch = tid >> 6;
        const float* src = Qb + (size_t)(q0 + r) * HD_ + ch * 16;
        #pragma unroll
        for (int i = 0; i < 4; i++) {
            float4 v = *(const float4*)(src + i * 4);
            int d = ch * 16 + i * 4;
            Qst[(d + 0) * 68 + r] = v.x * 0.125f;
            Qst[(d + 1) * 68 + r] = v.y * 0.125f;
            Qst[(d + 2) * 68 + r] = v.z * 0.125f;
            Qst[(d + 3) * 68 + r] = v.w * 0.125f;
        }
    }

    float m_i[4], l_i[4], acc[4][4];
    #pragma unroll
    for (int i = 0; i < 4; i++) {
        m_i[i] = -1e30f; l_i[i] = 0.f;
        #pragma unroll
        for (int j = 0; j < 4; j++) acc[i][j] = 0.f;
    }

    for (int t = 0; t < S_; t += 64) {
        // Load K (transposed) and V (natural) tiles
        {
            int r = tid & 63, ch = tid >> 6;
            const float* ks = Kb + (size_t)(t + r) * HD_ + ch * 16;
            const float* vv = Vb + (size_t)(t + r) * HD_ + ch * 16;
            #pragma unroll
            for (int i = 0; i < 4; i++) {
                float4 kq = *(const float4*)(ks + i * 4);
                int d = ch * 16 + i * 4;
                Kst[(d + 0) * 68 + r] = kq.x;
                Kst[(d + 1) * 68 + r] = kq.y;
                Kst[(d + 2) * 68 + r] = kq.z;
                Kst[(d + 3) * 68 + r] = kq.w;
                *(float4*)&Vs[r * 68 + d] = *(const float4*)(vv + i * 4);
            }
        }
        __syncthreads();

        // S = (Q*scale) K^T  : 4x4 microtile over 64-dim dot
        float s[4][4];
        #pragma unroll
        for (int i = 0; i < 4; i++)
            #pragma unroll
            for (int j = 0; j < 4; j++) s[i][j] = 0.f;

        #pragma unroll 8
        for (int d = 0; d < 64; d++) {
            float a[4], b[4];
            *(float4*)a = *(const float4*)&Qst[d * 68 + r0];
            *(float4*)b = *(const float4*)&Kst[d * 68 + c0];
            #pragma unroll
            for (int i = 0; i < 4; i++)
                #pragma unroll
                for (int j = 0; j < 4; j++)
                    s[i][j] += a[i] * b[j];
        }

        // Online softmax (per row, redundantly across the 16-thread row group)
        #pragma unroll
        for (int i = 0; i < 4; i++) {
            float rm = fmaxf(fmaxf(s[i][0], s[i][1]), fmaxf(s[i][2], s[i][3]));
            rm = fmaxf(rm, __shfl_xor_sync(0xffffffffu, rm, 1));
            rm = fmaxf(rm, __shfl_xor_sync(0xffffffffu, rm, 2));
            rm = fmaxf(rm, __shfl_xor_sync(0xffffffffu, rm, 4));
            rm = fmaxf(rm, __shfl_xor_sync(0xffffffffu, rm, 8));
            float mnew = fmaxf(m_i[i], rm);
            float al = __expf(m_i[i] - mnew);
            float rs = 0.f;
            float p[4];
            #pragma unroll
            for (int j = 0; j < 4; j++) {
                p[j] = __expf(s[i][j] - mnew);
                rs += p[j];
            }
            #pragma unroll
            for (int j = 0; j < 4; j++)
                Pt[(c0 + j) * 68 + r0 + i] = p[j];
            rs += __shfl_xor_sync(0xffffffffu, rs, 1);
            rs += __shfl_xor_sync(0xffffffffu, rs, 2);
            rs += __shfl_xor_sync(0xffffffffu, rs, 4);
            rs += __shfl_xor_sync(0xffffffffu, rs, 8);
            l_i[i] = l_i[i] * al + rs;
            m_i[i] = mnew;
            #pragma unroll
            for (int j = 0; j < 4; j++) acc[i][j] *= al;
        }
        __syncthreads();

        // O += P V : 4x4 microtile over 64 kv positions
        #pragma unroll 8
        for (int j = 0; j < 64; j++) {
            float a[4], b[4];
            *(float4*)a = *(const float4*)&Pt[j * 68 + r0];
            *(float4*)b = *(const float4*)&Vs[j * 68 + c0];
            #pragma unroll
            for (int i = 0; i < 4; i++)
                #pragma unroll
                for (int jj = 0; jj < 4; jj++)
                    acc[i][jj] += a[i] * b[jj];
        }
        __syncthreads();
    }

    // Epilogue: normalize and write to [b, s, h*64+hd]
    int bb = bh / H_, h = bh % H_;
    #pragma unroll
    for (int i = 0; i < 4; i++) {
        float inv = 1.0f / l_i[i];
        float4 o;
        o.x = acc[i][0] * inv;
        o.y = acc[i][1] * inv;
        o.z = acc[i][2] * inv;
        o.w = acc[i][3] * inv;
        *(float4*)&g_ao[((size_t)(bb * S_ + q0 + r0 + i)) * D_ + h * HD_ + c0] = o;
    }
}

// ---------------------------------------------------------------------------
extern "C" void kernel_launch(void* const* d_in, const int* in_sizes, int n_in,
                              void* d_out, int out_size)
{
    const float* x  = (const float*)d_in[0];
    const float* Wq = (const float*)d_in[1];
    const float* bq = (const float*)d_in[2];
    const float* Wk = (const float*)d_in[3];
    const float* bk = (const float*)d_in[4];
    const float* Wv = (const float*)d_in[5];
    const float* bv = (const float*)d_in[6];
    const float* Wo = (const float*)d_in[7];
    const float* bo = (const float*)d_in[8];
    float* out = (float*)d_out;

    dim3 gGemm(D_ / 128, M_ / 128);       // (8, 32)
    gemm_kernel<1><<<gGemm, 256>>>(x, Wq, bq, nullptr);
    gemm_kernel<2><<<gGemm, 256>>>(x, Wk, bk, nullptr);
    gemm_kernel<3><<<gGemm, 256>>>(x, Wv, bv, nullptr);

    const int attn_smem = 4 * 64 * 68 * sizeof(float);   // 69632 B
    cudaFuncSetAttribute(attn_kernel,
                         cudaFuncAttributeMaxDynamicSharedMemorySize, attn_smem);
    dim3 gAttn(S_ / 64, B_ * H_);         // (32, 32)
    attn_kernel<<<gAttn, 256, attn_smem>>>();

    gemm_kernel<0><<<gGemm, 256>>>(nullptr, Wo, bo, out);
}

// round 3
// speedup vs baseline: 1.4303x; 1.4303x over previous
#include <cuda_runtime.h>
#include <cstdint>

#define B_  2
#define S_  2048
#define D_  1024
#define H_  16
#define HD_ 64
#define M_  (B_*S_)   // 4096

// ---------------------------------------------------------------------------
// Scratch (allocation-free rule: __device__ globals)
// ---------------------------------------------------------------------------
__device__ float g_q[B_*H_*S_*HD_];   // [b,h,s,hd]
__device__ float g_k[B_*H_*S_*HD_];
__device__ float g_v[B_*H_*S_*HD_];
__device__ float g_ao[M_*D_];         // attention out, [b,s, h*hd]
__device__ float g_wt[4*D_*D_];       // transposed weights: [n][k] for Wq,Wk,Wv,Wo

// ---------------------------------------------------------------------------
__device__ __forceinline__ float to_tf32(float x) {
    uint32_t u;
    asm("cvt.rna.tf32.f32 %0, %1;" : "=r"(u) : "f"(x));
    return __uint_as_float(u);
}

// D += A * B  (m16n8k8, tf32 inputs, f32 accum)
__device__ __forceinline__ void mma_tf32(float* d, const uint32_t* a, const uint32_t* b) {
    asm volatile(
        "mma.sync.aligned.m16n8k8.row.col.f32.tf32.tf32.f32 "
        "{%0,%1,%2,%3}, {%4,%5,%6,%7}, {%8,%9}, {%0,%1,%2,%3};"
        : "+f"(d[0]), "+f"(d[1]), "+f"(d[2]), "+f"(d[3])
        : "r"(a[0]), "r"(a[1]), "r"(a[2]), "r"(a[3]), "r"(b[0]), "r"(b[1]));
}

// ---------------------------------------------------------------------------
// Weight transpose: dst[n][k] = src[k][n]   (1024x1024)
// ---------------------------------------------------------------------------
__global__ __launch_bounds__(256)
void transpose_kernel(const float* __restrict__ src, int widx)
{
    __shared__ float t[32][33];
    float* dst = g_wt + (size_t)widx * D_ * D_;
    int bx = blockIdx.x * 32, by = blockIdx.y * 32;
    int tx = threadIdx.x, ty = threadIdx.y;
    #pragma unroll
    for (int i = 0; i < 32; i += 8)
        t[ty + i][tx] = src[(size_t)(by + ty + i) * D_ + bx + tx];
    __syncthreads();
    #pragma unroll
    for (int i = 0; i < 32; i += 8)
        dst[(size_t)(bx + ty + i) * D_ + by + tx] = t[tx][ty + i];
}

// ---------------------------------------------------------------------------
// tf32 mma.sync GEMM: C[m][n] = A[m][:] . Wt[n][:] + bias[n]
// MODE 0: A=g_ao, Wt=g_wt[3], out=outp row-major [M,D]
// MODE 1/2/3: A=x, Wt=g_wt[0/1/2], out=g_q/g_k/g_v scattered to [b,h,s,hd]
// CTA 128x128, 256 thr, 8 warps (2x4), warp tile 64x32, K chunks of 32.
// ---------------------------------------------------------------------------
template<int MODE>
__global__ __launch_bounds__(256)
void gemm_mma_kernel(const float* __restrict__ Ap,
                     const float* __restrict__ bias,
                     float* __restrict__ outp)
{
    __shared__ float As[128][36];   // [m][k], pad 4 -> conflict-free frag loads
    __shared__ float Bs[128][36];   // [n][k]

    const int tid = threadIdx.x;
    const int wid = tid >> 5, lid = tid & 31;
    const int g = lid >> 2, tig = lid & 3;
    const int wm = (wid >> 2) * 64;      // warp row offset (0/64)
    const int wn = (wid & 3) * 32;       // warp col offset (0/32/64/96)
    const int bm = blockIdx.y * 128;
    const int bn = blockIdx.x * 128;

    const float* A  = (MODE == 0) ? (const float*)g_ao : Ap;
    const float* Bt = g_wt + (size_t)((MODE == 0) ? 3 : (MODE - 1)) * D_ * D_;

    float acc[4][4][4];
    #pragma unroll
    for (int mb = 0; mb < 4; mb++)
        #pragma unroll
        for (int nb = 0; nb < 4; nb++)
            #pragma unroll
            for (int i = 0; i < 4; i++) acc[mb][nb][i] = 0.f;

    for (int c = 0; c < D_ / 32; c++) {
        const int k0 = c * 32;
        // cooperative load: 128x32 A and B tiles, RNA-rounded to tf32
        #pragma unroll
        for (int i = 0; i < 4; i++) {
            int idx = tid + i * 256;
            int row = idx >> 3, v = (idx & 7) * 4;
            float4 av = *(const float4*)&A [(size_t)(bm + row) * D_ + k0 + v];
            float4 bv = *(const float4*)&Bt[(size_t)(bn + row) * D_ + k0 + v];
            av.x = to_tf32(av.x); av.y = to_tf32(av.y);
            av.z = to_tf32(av.z); av.w = to_tf32(av.w);
            bv.x = to_tf32(bv.x); bv.y = to_tf32(bv.y);
            bv.z = to_tf32(bv.z); bv.w = to_tf32(bv.w);
            *(float4*)&As[row][v] = av;
            *(float4*)&Bs[row][v] = bv;
        }
        __syncthreads();

        #pragma unroll
        for (int ks = 0; ks < 4; ks++) {
            const int k = ks * 8;
            uint32_t af[4][4], bf[4][2];
            #pragma unroll
            for (int mb = 0; mb < 4; mb++) {
                int m = wm + mb * 16 + g;
                af[mb][0] = __float_as_uint(As[m    ][k + tig]);
                af[mb][1] = __float_as_uint(As[m + 8][k + tig]);
                af[mb][2] = __float_as_uint(As[m    ][k + tig + 4]);
                af[mb][3] = __float_as_uint(As[m + 8][k + tig + 4]);
            }
            #pragma unroll
            for (int nb = 0; nb < 4; nb++) {
                int n = wn + nb * 8 + g;
                bf[nb][0] = __float_as_uint(Bs[n][k + tig]);
                bf[nb][1] = __float_as_uint(Bs[n][k + tig + 4]);
            }
            #pragma unroll
            for (int mb = 0; mb < 4; mb++)
                #pragma unroll
                for (int nb = 0; nb < 4; nb++)
                    mma_tf32(acc[mb][nb], af[mb], bf[nb]);
        }
        __syncthreads();
    }

    // Epilogue: c0/c1 -> (row g, cols 2tig,2tig+1), c2/c3 -> row g+8
    float* qkv = (MODE == 1) ? g_q : (MODE == 2) ? g_k : g_v;
    #pragma unroll
    for (int mb = 0; mb < 4; mb++) {
        #pragma unroll
        for (int half = 0; half < 2; half++) {
            const int m = bm + wm + mb * 16 + g + half * 8;
            #pragma unroll
            for (int nb = 0; nb < 4; nb++) {
                const int n = bn + wn + nb * 8 + 2 * tig;
                float2 o;
                o.x = acc[mb][nb][half * 2 + 0] + __ldg(&bias[n]);
                o.y = acc[mb][nb][half * 2 + 1] + __ldg(&bias[n + 1]);
                if (MODE == 0) {
                    *(float2*)&outp[(size_t)m * D_ + n] = o;
                } else {
                    int b = m >> 11, s = m & 2047;
                    int h = n >> 6,  hd = n & 63;
                    *(float2*)&qkv[(((size_t)(b * H_ + h)) * S_ + s) * HD_ + hd] = o;
                }
            }
        }
    }
}

// ---------------------------------------------------------------------------
// Flash attention (R1-validated): per (b*H+h, 64-row q tile), fp32 scalar.
// ---------------------------------------------------------------------------
__global__ __launch_bounds__(256)
void attn_kernel()
{
    extern __shared__ float sm[];
    float* Qst = sm;                  // [d][r], pre-scaled by 1/8
    float* Kst = sm + 64 * 68;        // [d][c]
    float* Pt  = sm + 2 * 64 * 68;    // [j][r]
    float* Vs  = sm + 3 * 64 * 68;    // [j][d]

    const int tid = threadIdx.x;
    const int tx = tid & 15, ty = tid >> 4;
    const int r0 = ty * 4, c0 = tx * 4;
    const int bh = blockIdx.y;
    const int q0 = blockIdx.x * 64;

    const float* Qb = g_q + (size_t)bh * S_ * HD_;
    const float* Kb = g_k + (size_t)bh * S_ * HD_;
    const float* Vb = g_v + (size_t)bh * S_ * HD_;

    {
        int r = tid & 63, ch = tid >> 6;
        const float* src = Qb + (size_t)(q0 + r) * HD_ + ch * 16;
        #pragma unroll
        for (int i = 0; i < 4; i++) {
            float4 v = *(const float4*)(src + i * 4);
            int d = ch * 16 + i * 4;
            Qst[(d + 0) * 68 + r] = v.x * 0.125f;
            Qst[(d + 1) * 68 + r] = v.y * 0.125f;
            Qst[(d + 2) * 68 + r] = v.z * 0.125f;
            Qst[(d + 3) * 68 + r] = v.w * 0.125f;
        }
    }

    float m_i[4], l_i[4], acc[4][4];
    #pragma unroll
    for (int i = 0; i < 4; i++) {
        m_i[i] = -1e30f; l_i[i] = 0.f;
        #pragma unroll
        for (int j = 0; j < 4; j++) acc[i][j] = 0.f;
    }

    for (int t = 0; t < S_; t += 64) {
        {
            int r = tid & 63, ch = tid >> 6;
            const float* ks = Kb + (size_t)(t + r) * HD_ + ch * 16;
            const float* vv = Vb + (size_t)(t + r) * HD_ + ch * 16;
            #pragma unroll
            for (int i = 0; i < 4; i++) {
                float4 kq = *(const float4*)(ks + i * 4);
                int d = ch * 16 + i * 4;
                Kst[(d + 0) * 68 + r] = kq.x;
                Kst[(d + 1) * 68 + r] = kq.y;
                Kst[(d + 2) * 68 + r] = kq.z;
                Kst[(d + 3) * 68 + r] = kq.w;
                *(float4*)&Vs[r * 68 + d] = *(const float4*)(vv + i * 4);
            }
        }
        __syncthreads();

        float s[4][4];
        #pragma unroll
        for (int i = 0; i < 4; i++)
            #pragma unroll
            for (int j = 0; j < 4; j++) s[i][j] = 0.f;

        #pragma unroll 8
        for (int d = 0; d < 64; d++) {
            float a[4], b[4];
            *(float4*)a = *(const float4*)&Qst[d * 68 + r0];
            *(float4*)b = *(const float4*)&Kst[d * 68 + c0];
            #pragma unroll
            for (int i = 0; i < 4; i++)
                #pragma unroll
                for (int j = 0; j < 4; j++)
                    s[i][j] += a[i] * b[j];
        }

        #pragma unroll
        for (int i = 0; i < 4; i++) {
            float rm = fmaxf(fmaxf(s[i][0], s[i][1]), fmaxf(s[i][2], s[i][3]));
            rm = fmaxf(rm, __shfl_xor_sync(0xffffffffu, rm, 1));
            rm = fmaxf(rm, __shfl_xor_sync(0xffffffffu, rm, 2));
            rm = fmaxf(rm, __shfl_xor_sync(0xffffffffu, rm, 4));
            rm = fmaxf(rm, __shfl_xor_sync(0xffffffffu, rm, 8));
            float mnew = fmaxf(m_i[i], rm);
            float al = __expf(m_i[i] - mnew);
            float rs = 0.f;
            float p[4];
            #pragma unroll
            for (int j = 0; j < 4; j++) {
                p[j] = __expf(s[i][j] - mnew);
                rs += p[j];
            }
            #pragma unroll
            for (int j = 0; j < 4; j++)
                Pt[(c0 + j) * 68 + r0 + i] = p[j];
            rs += __shfl_xor_sync(0xffffffffu, rs, 1);
            rs += __shfl_xor_sync(0xffffffffu, rs, 2);
            rs += __shfl_xor_sync(0xffffffffu, rs, 4);
            rs += __shfl_xor_sync(0xffffffffu, rs, 8);
            l_i[i] = l_i[i] * al + rs;
            m_i[i] = mnew;
            #pragma unroll
            for (int j = 0; j < 4; j++) acc[i][j] *= al;
        }
        __syncthreads();

        #pragma unroll 8
        for (int j = 0; j < 64; j++) {
            float a[4], b[4];
            *(float4*)a = *(const float4*)&Pt[j * 68 + r0];
            *(float4*)b = *(const float4*)&Vs[j * 68 + c0];
            #pragma unroll
            for (int i = 0; i < 4; i++)
                #pragma unroll
                for (int jj = 0; jj < 4; jj++)
                    acc[i][jj] += a[i] * b[jj];
        }
        __syncthreads();
    }

    int bb = bh / H_, h = bh % H_;
    #pragma unroll
    for (int i = 0; i < 4; i++) {
        float inv = 1.0f / l_i[i];
        float4 o;
        o.x = acc[i][0] * inv;
        o.y = acc[i][1] * inv;
        o.z = acc[i][2] * inv;
        o.w = acc[i][3] * inv;
        *(float4*)&g_ao[((size_t)(bb * S_ + q0 + r0 + i)) * D_ + h * HD_ + c0] = o;
    }
}

// ---------------------------------------------------------------------------
extern "C" void kernel_launch(void* const* d_in, const int* in_sizes, int n_in,
                              void* d_out, int out_size)
{
    const float* x  = (const float*)d_in[0];
    const float* Wq = (const float*)d_in[1];
    const float* bq = (const float*)d_in[2];
    const float* Wk = (const float*)d_in[3];
    const float* bk = (const float*)d_in[4];
    const float* Wv = (const float*)d_in[5];
    const float* bv = (const float*)d_in[6];
    const float* Wo = (const float*)d_in[7];
    const float* bo = (const float*)d_in[8];
    float* out = (float*)d_out;

    static bool attr_done = false;
    if (!attr_done) {
        cudaFuncSetAttribute(attn_kernel, cudaFuncAttributeMaxDynamicSharedMemorySize,
                             4 * 64 * 68 * 4);
        attr_done = true;
    }

    dim3 gT(D_ / 32, D_ / 32);
    transpose_kernel<<<gT, dim3(32, 8)>>>(Wq, 0);
    transpose_kernel<<<gT, dim3(32, 8)>>>(Wk, 1);
    transpose_kernel<<<gT, dim3(32, 8)>>>(Wv, 2);
    transpose_kernel<<<gT, dim3(32, 8)>>>(Wo, 3);

    dim3 gG(D_ / 128, M_ / 128);   // (8, 32)
    gemm_mma_kernel<1><<<gG, 256>>>(x, bq, nullptr);
    gemm_mma_kernel<2><<<gG, 256>>>(x, bk, nullptr);
    gemm_mma_kernel<3><<<gG, 256>>>(x, bv, nullptr);

    const int attn_smem = 4 * 64 * 68 * sizeof(float);
    dim3 gAttn(S_ / 64, B_ * H_);
    attn_kernel<<<gAttn, 256, attn_smem>>>();

    gemm_mma_kernel<0><<<gG, 256>>>(nullptr, bo, out);
}

// round 4
// speedup vs baseline: 3.3459x; 2.3393x over previous
#include <cuda_runtime.h>
#include <cstdint>

#define B_  2
#define S_  2048
#define D_  1024
#define H_  16
#define HD_ 64
#define M_  (B_*S_)   // 4096

// ---------------------------------------------------------------------------
// Scratch (allocation-free rule: __device__ globals)
// ---------------------------------------------------------------------------
__device__ float g_q[B_*H_*S_*HD_];   // [b,h,s,hd]
__device__ float g_k[B_*H_*S_*HD_];
__device__ float g_v[B_*H_*S_*HD_];
__device__ float g_ao[M_*D_];         // attention out, [b,s, h*hd]
__device__ float g_wt[4*D_*D_];       // transposed weights: [n][k]

// ---------------------------------------------------------------------------
__device__ __forceinline__ float to_tf32(float x) {
    uint32_t u;
    asm("cvt.rna.tf32.f32 %0, %1;" : "=r"(u) : "f"(x));
    return __uint_as_float(u);
}

__device__ __forceinline__ void mma_tf32(float* d, const uint32_t* a, const uint32_t* b) {
    asm volatile(
        "mma.sync.aligned.m16n8k8.row.col.f32.tf32.tf32.f32 "
        "{%0,%1,%2,%3}, {%4,%5,%6,%7}, {%8,%9}, {%0,%1,%2,%3};"
        : "+f"(d[0]), "+f"(d[1]), "+f"(d[2]), "+f"(d[3])
        : "r"(a[0]), "r"(a[1]), "r"(a[2]), "r"(a[3]), "r"(b[0]), "r"(b[1]));
}

// ---------------------------------------------------------------------------
// Weight transpose: dst[n][k] = src[k][n]   (1024x1024)
// ---------------------------------------------------------------------------
__global__ __launch_bounds__(256)
void transpose_kernel(const float* __restrict__ src, int widx)
{
    __shared__ float t[32][33];
    float* dst = g_wt + (size_t)widx * D_ * D_;
    int bx = blockIdx.x * 32, by = blockIdx.y * 32;
    int tx = threadIdx.x, ty = threadIdx.y;
    #pragma unroll
    for (int i = 0; i < 32; i += 8)
        t[ty + i][tx] = src[(size_t)(by + ty + i) * D_ + bx + tx];
    __syncthreads();
    #pragma unroll
    for (int i = 0; i < 32; i += 8)
        dst[(size_t)(bx + ty + i) * D_ + by + tx] = t[tx][ty + i];
}

// ---------------------------------------------------------------------------
// tf32 mma.sync GEMM (validated R3): C = A . Wt^T + bias
// ---------------------------------------------------------------------------
template<int MODE>
__global__ __launch_bounds__(256)
void gemm_mma_kernel(const float* __restrict__ Ap,
                     const float* __restrict__ bias,
                     float* __restrict__ outp)
{
    __shared__ float As[128][36];
    __shared__ float Bs[128][36];

    const int tid = threadIdx.x;
    const int wid = tid >> 5, lid = tid & 31;
    const int g = lid >> 2, tig = lid & 3;
    const int wm = (wid >> 2) * 64;
    const int wn = (wid & 3) * 32;
    const int bm = blockIdx.y * 128;
    const int bn = blockIdx.x * 128;

    const float* A  = (MODE == 0) ? (const float*)g_ao : Ap;
    const float* Bt = g_wt + (size_t)((MODE == 0) ? 3 : (MODE - 1)) * D_ * D_;

    float acc[4][4][4];
    #pragma unroll
    for (int mb = 0; mb < 4; mb++)
        #pragma unroll
        for (int nb = 0; nb < 4; nb++)
            #pragma unroll
            for (int i = 0; i < 4; i++) acc[mb][nb][i] = 0.f;

    for (int c = 0; c < D_ / 32; c++) {
        const int k0 = c * 32;
        #pragma unroll
        for (int i = 0; i < 4; i++) {
            int idx = tid + i * 256;
            int row = idx >> 3, v = (idx & 7) * 4;
            float4 av = *(const float4*)&A [(size_t)(bm + row) * D_ + k0 + v];
            float4 bv = *(const float4*)&Bt[(size_t)(bn + row) * D_ + k0 + v];
            av.x = to_tf32(av.x); av.y = to_tf32(av.y);
            av.z = to_tf32(av.z); av.w = to_tf32(av.w);
            bv.x = to_tf32(bv.x); bv.y = to_tf32(bv.y);
            bv.z = to_tf32(bv.z); bv.w = to_tf32(bv.w);
            *(float4*)&As[row][v] = av;
            *(float4*)&Bs[row][v] = bv;
        }
        __syncthreads();

        #pragma unroll
        for (int ks = 0; ks < 4; ks++) {
            const int k = ks * 8;
            uint32_t af[4][4], bf[4][2];
            #pragma unroll
            for (int mb = 0; mb < 4; mb++) {
                int m = wm + mb * 16 + g;
                af[mb][0] = __float_as_uint(As[m    ][k + tig]);
                af[mb][1] = __float_as_uint(As[m + 8][k + tig]);
                af[mb][2] = __float_as_uint(As[m    ][k + tig + 4]);
                af[mb][3] = __float_as_uint(As[m + 8][k + tig + 4]);
            }
            #pragma unroll
            for (int nb = 0; nb < 4; nb++) {
                int n = wn + nb * 8 + g;
                bf[nb][0] = __float_as_uint(Bs[n][k + tig]);
                bf[nb][1] = __float_as_uint(Bs[n][k + tig + 4]);
            }
            #pragma unroll
            for (int mb = 0; mb < 4; mb++)
                #pragma unroll
                for (int nb = 0; nb < 4; nb++)
                    mma_tf32(acc[mb][nb], af[mb], bf[nb]);
        }
        __syncthreads();
    }

    float* qkv = (MODE == 1) ? g_q : (MODE == 2) ? g_k : g_v;
    #pragma unroll
    for (int mb = 0; mb < 4; mb++) {
        #pragma unroll
        for (int half = 0; half < 2; half++) {
            const int m = bm + wm + mb * 16 + g + half * 8;
            #pragma unroll
            for (int nb = 0; nb < 4; nb++) {
                const int n = bn + wn + nb * 8 + 2 * tig;
                float2 o;
                o.x = acc[mb][nb][half * 2 + 0] + __ldg(&bias[n]);
                o.y = acc[mb][nb][half * 2 + 1] + __ldg(&bias[n + 1]);
                if (MODE == 0) {
                    *(float2*)&outp[(size_t)m * D_ + n] = o;
                } else {
                    int b = m >> 11, s = m & 2047;
                    int h = n >> 6,  hd = n & 63;
                    *(float2*)&qkv[(((size_t)(b * H_ + h)) * S_ + s) * HD_ + hd] = o;
                }
            }
        }
    }
}

// ---------------------------------------------------------------------------
// Flash attention, tf32 mma.sync.
// CTA: 128 q rows x full head. 8 warps, warp w owns q rows [16w, 16w+16),
// all 64 kv cols of each tile -> softmax fully warp-local.
// Per 64-kv tile: S = Q.K^T (mma), online softmax (shfl xor 1,2), P to
// warp-private smem, O += P.V with V transposed in smem.
// Pitch 68 floats: fragment loads hit bank (4g+tig)=lane -> conflict-free.
// ---------------------------------------------------------------------------
#define AP 68
#define ATT_SMEM (384 * AP * 4)   // Qs 128 + Ks 64 + Vt 64 + Ps 128 rows

__global__ __launch_bounds__(256, 2)
void attn_mma_kernel()
{
    extern __shared__ float sm[];
    float* Qs = sm;                 // [128][AP]  (q x hd, pre-scaled, tf32)
    float* Ks = sm + 128 * AP;      // [64][AP]   (kv x hd, tf32)
    float* Vt = sm + 192 * AP;      // [64][AP]   (hd x kv, tf32)
    float* Ps = sm + 256 * AP;      // [128][AP]  (q x kv, tf32)

    const int tid = threadIdx.x;
    const int wid = tid >> 5, lid = tid & 31;
    const int g = lid >> 2, tig = lid & 3;
    const int wq = wid * 16;
    const int bh = blockIdx.y;
    const int q0 = blockIdx.x * 128;

    const float* Qb = g_q + (size_t)bh * S_ * HD_;
    const float* Kb = g_k + (size_t)bh * S_ * HD_;
    const float* Vb = g_v + (size_t)bh * S_ * HD_;

    // Load Q tile (128 x 64), fold 1/8 scale, tf32-round
    #pragma unroll
    for (int i = 0; i < 8; i++) {
        int idx = tid + i * 256;
        int r = idx >> 4, c4 = (idx & 15) * 4;
        float4 v = *(const float4*)&Qb[(size_t)(q0 + r) * HD_ + c4];
        Qs[r * AP + c4 + 0] = to_tf32(v.x * 0.125f);
        Qs[r * AP + c4 + 1] = to_tf32(v.y * 0.125f);
        Qs[r * AP + c4 + 2] = to_tf32(v.z * 0.125f);
        Qs[r * AP + c4 + 3] = to_tf32(v.w * 0.125f);
    }

    float m_i[2] = {-1e30f, -1e30f}, l_i[2] = {0.f, 0.f};
    float acc[8][4];
    #pragma unroll
    for (int nb = 0; nb < 8; nb++)
        #pragma unroll
        for (int i = 0; i < 4; i++) acc[nb][i] = 0.f;

    for (int t = 0; t < S_; t += 64) {
        __syncthreads();   // previous tile's Ks/Vt reads complete
        // K natural [kv][hd] (float4 stores, 4-phase min, conflict-free octets)
        #pragma unroll
        for (int i = 0; i < 4; i++) {
            int idx = tid + i * 256;
            int r = idx >> 4, c4 = (idx & 15) * 4;
            float4 kq = *(const float4*)&Kb[(size_t)(t + r) * HD_ + c4];
            Ks[r * AP + c4 + 0] = to_tf32(kq.x);
            Ks[r * AP + c4 + 1] = to_tf32(kq.y);
            Ks[r * AP + c4 + 2] = to_tf32(kq.z);
            Ks[r * AP + c4 + 3] = to_tf32(kq.w);
        }
        // V transposed [hd][kv]: idx mapping gives conflict-free scalar
        // stores (bank = 16*(idx&1) + r mod 32) and full 32B-sector use.
        #pragma unroll
        for (int i = 0; i < 4; i++) {
            int idx = tid + i * 256;
            int r = (idx >> 1) & 63;
            int c4 = ((idx & 1) | ((idx >> 7) << 1)) * 4;
            float4 vv = *(const float4*)&Vb[(size_t)(t + r) * HD_ + c4];
            Vt[(c4 + 0) * AP + r] = to_tf32(vv.x);
            Vt[(c4 + 1) * AP + r] = to_tf32(vv.y);
            Vt[(c4 + 2) * AP + r] = to_tf32(vv.z);
            Vt[(c4 + 3) * AP + r] = to_tf32(vv.w);
        }
        __syncthreads();

        // S = Q K^T : rows wq+g/wq+g+8, col frags nb*8 + {2tig, 2tig+1}
        float s[8][4];
        #pragma unroll
        for (int nb = 0; nb < 8; nb++)
            #pragma unroll
            for (int i = 0; i < 4; i++) s[nb][i] = 0.f;

        #pragma unroll
        for (int kk = 0; kk < 64; kk += 8) {
            uint32_t af[4];
            af[0] = __float_as_uint(Qs[(wq + g    ) * AP + kk + tig]);
            af[1] = __float_as_uint(Qs[(wq + g + 8) * AP + kk + tig]);
            af[2] = __float_as_uint(Qs[(wq + g    ) * AP + kk + tig + 4]);
            af[3] = __float_as_uint(Qs[(wq + g + 8) * AP + kk + tig + 4]);
            #pragma unroll
            for (int nb = 0; nb < 8; nb++) {
                uint32_t bf[2];
                bf[0] = __float_as_uint(Ks[(nb * 8 + g) * AP + kk + tig]);
                bf[1] = __float_as_uint(Ks[(nb * 8 + g) * AP + kk + tig + 4]);
                mma_tf32(s[nb], af, bf);
            }
        }

        // Online softmax (rows wq+g and wq+g+8; reduce over tig via xor 1,2)
        float mx[2] = {-1e30f, -1e30f};
        #pragma unroll
        for (int nb = 0; nb < 8; nb++) {
            mx[0] = fmaxf(mx[0], fmaxf(s[nb][0], s[nb][1]));
            mx[1] = fmaxf(mx[1], fmaxf(s[nb][2], s[nb][3]));
        }
        #pragma unroll
        for (int h = 0; h < 2; h++) {
            mx[h] = fmaxf(mx[h], __shfl_xor_sync(0xffffffffu, mx[h], 1));
            mx[h] = fmaxf(mx[h], __shfl_xor_sync(0xffffffffu, mx[h], 2));
        }
        float mnew[2], al[2], rs[2] = {0.f, 0.f};
        #pragma unroll
        for (int h = 0; h < 2; h++) {
            mnew[h] = fmaxf(m_i[h], mx[h]);
            al[h] = __expf(m_i[h] - mnew[h]);
            m_i[h] = mnew[h];
        }
        #pragma unroll
        for (int nb = 0; nb < 8; nb++) {
            s[nb][0] = __expf(s[nb][0] - mnew[0]);
            s[nb][1] = __expf(s[nb][1] - mnew[0]);
            s[nb][2] = __expf(s[nb][2] - mnew[1]);
            s[nb][3] = __expf(s[nb][3] - mnew[1]);
            rs[0] += s[nb][0] + s[nb][1];
            rs[1] += s[nb][2] + s[nb][3];
        }
        #pragma unroll
        for (int h = 0; h < 2; h++) {
            rs[h] += __shfl_xor_sync(0xffffffffu, rs[h], 1);
            rs[h] += __shfl_xor_sync(0xffffffffu, rs[h], 2);
            l_i[h] = l_i[h] * al[h] + rs[h];
        }
        #pragma unroll
        for (int nb = 0; nb < 8; nb++) {
            acc[nb][0] *= al[0]; acc[nb][1] *= al[0];
            acc[nb][2] *= al[1]; acc[nb][3] *= al[1];
        }

        // P to warp-private smem rows (tf32)
        #pragma unroll
        for (int nb = 0; nb < 8; nb++) {
            float2 p0 = make_float2(to_tf32(s[nb][0]), to_tf32(s[nb][1]));
            float2 p1 = make_float2(to_tf32(s[nb][2]), to_tf32(s[nb][3]));
            *(float2*)&Ps[(wq + g    ) * AP + nb * 8 + 2 * tig] = p0;
            *(float2*)&Ps[(wq + g + 8) * AP + nb * 8 + 2 * tig] = p1;
        }
        __syncwarp();

        // O += P V  (contract over kv; B = Vt[hd][kv])
        #pragma unroll
        for (int kk = 0; kk < 64; kk += 8) {
            uint32_t af[4];
            af[0] = __float_as_uint(Ps[(wq + g    ) * AP + kk + tig]);
            af[1] = __float_as_uint(Ps[(wq + g + 8) * AP + kk + tig]);
            af[2] = __float_as_uint(Ps[(wq + g    ) * AP + kk + tig + 4]);
            af[3] = __float_as_uint(Ps[(wq + g + 8) * AP + kk + tig + 4]);
            #pragma unroll
            for (int nb = 0; nb < 8; nb++) {
                uint32_t bf[2];
                bf[0] = __float_as_uint(Vt[(nb * 8 + g) * AP + kk + tig]);
                bf[1] = __float_as_uint(Vt[(nb * 8 + g) * AP + kk + tig + 4]);
                mma_tf32(acc[nb], af, bf);
            }
        }
        __syncwarp();   // P reads done before next tile overwrites
    }

    // Epilogue: normalize, write to g_ao [b, s, h*64 + col]
    const int bb = bh / H_, h = bh % H_;
    const float inv0 = 1.0f / l_i[0], inv1 = 1.0f / l_i[1];
    const int s0 = q0 + wq + g;
    #pragma unroll
    for (int nb = 0; nb < 8; nb++) {
        const int col = h * HD_ + nb * 8 + 2 * tig;
        float2 o0 = make_float2(acc[nb][0] * inv0, acc[nb][1] * inv0);
        float2 o1 = make_float2(acc[nb][2] * inv1, acc[nb][3] * inv1);
        *(float2*)&g_ao[(size_t)(bb * S_ + s0    ) * D_ + col] = o0;
        *(float2*)&g_ao[(size_t)(bb * S_ + s0 + 8) * D_ + col] = o1;
    }
}

// ---------------------------------------------------------------------------
extern "C" void kernel_launch(void* const* d_in, const int* in_sizes, int n_in,
                              void* d_out, int out_size)
{
    const float* x  = (const float*)d_in[0];
    const float* Wq = (const float*)d_in[1];
    const float* bq = (const float*)d_in[2];
    const float* Wk = (const float*)d_in[3];
    const float* bk = (const float*)d_in[4];
    const float* Wv = (const float*)d_in[5];
    const float* bv = (const float*)d_in[6];
    const float* Wo = (const float*)d_in[7];
    const float* bo = (const float*)d_in[8];
    float* out = (float*)d_out;

    static bool attr_done = false;
    if (!attr_done) {
        cudaFuncSetAttribute(attn_mma_kernel,
                             cudaFuncAttributeMaxDynamicSharedMemorySize, ATT_SMEM);
        attr_done = true;
    }

    dim3 gT(D_ / 32, D_ / 32);
    transpose_kernel<<<gT, dim3(32, 8)>>>(Wq, 0);
    transpose_kernel<<<gT, dim3(32, 8)>>>(Wk, 1);
    transpose_kernel<<<gT, dim3(32, 8)>>>(Wv, 2);
    transpose_kernel<<<gT, dim3(32, 8)>>>(Wo, 3);

    dim3 gG(D_ / 128, M_ / 128);   // (8, 32)
    gemm_mma_kernel<1><<<gG, 256>>>(x, bq, nullptr);
    gemm_mma_kernel<2><<<gG, 256>>>(x, bk, nullptr);
    gemm_mma_kernel<3><<<gG, 256>>>(x, bv, nullptr);

    dim3 gAttn(S_ / 128, B_ * H_);  // (16, 32)
    attn_mma_kernel<<<gAttn, 256, ATT_SMEM>>>();

    gemm_mma_kernel<0><<<gG, 256>>>(nullptr, bo, out);
}